// round 1
// baseline (speedup 1.0000x reference)
#include <cuda_runtime.h>
#include <cstdint>

// CIN (xDeepFM) fused kernel: one CTA per batch row.
// x0 gather -> 3 CIN layers as SMEM-resident GEMMs with on-the-fly
// outer-product B generation -> sum over embedding dim.

#define BATCH 2048
#define FIELD 39
#define DIM   64
#define KT    32          // k-tile
#define NTHR  256

#define L0 256
#define L1 128
#define L2 64
#define LTOT (L0 + L1 + L2)   // 448

// ---- packed f32x2 helpers (Blackwell) ----
__device__ __forceinline__ unsigned long long dup2(float v) {
    unsigned long long r;
    asm("mov.b64 %0, {%1, %1};" : "=l"(r) : "f"(v));
    return r;
}
__device__ __forceinline__ void fma2(unsigned long long& d,
                                     unsigned long long a,
                                     unsigned long long b) {
    asm("fma.rn.f32x2 %0, %1, %2, %3;" : "=l"(d) : "l"(a), "l"(b), "l"(d));
}
__device__ __forceinline__ float2 unpack2(unsigned long long v) {
    float2 f;
    asm("mov.b64 {%0, %1}, %2;" : "=f"(f.x), "=f"(f.y) : "l"(v));
    return f;
}

// SMEM layout (floats):
//  x0s   : 39*64   = 2496
//  h0    : 256*64  = 16384
//  h1    : 128*64  = 8192
//  h2    : 64*64   = 4096
//  Ws    : 32*256  = 8192   (k-tile of W, [kk][l])
//  Bs    : 32*64   = 2048   (k-tile of P, [kk][d])
#define OFF_X0 0
#define OFF_H0 (OFF_X0 + FIELD * DIM)
#define OFF_H1 (OFF_H0 + L0 * DIM)
#define OFF_H2 (OFF_H1 + L1 * DIM)
#define OFF_WS (OFF_H2 + L2 * DIM)
#define OFF_BS (OFF_WS + KT * L0)
#define SMEM_FLOATS (OFF_BS + KT * DIM)
#define SMEM_BYTES (SMEM_FLOATS * 4)

// One CIN layer: C[L,64] = W^T[L,K] * P[K,64], P[(i,j),d]=x0[i,d]*hprev[j,d]
// W stored row-major [K, L] (k slow, l fast) so W tiles are contiguous.
template<int L, int FK>
__device__ __forceinline__ void cin_layer(
    const float* __restrict__ Wg, const float* __restrict__ bias,
    const float* __restrict__ x0s, const float* __restrict__ hprev,
    float* __restrict__ hout, float* __restrict__ Ws, float* __restrict__ Bs)
{
    const int tid = threadIdx.x;
    const int tr  = tid >> 4;          // 0..15 -> l-group
    const int tc  = tid & 15;          // 0..15 -> d-group
    constexpr int TL = L / 16;         // l's per thread (16/8/4)
    constexpr int NP = TL / 2;         // packed l-pairs per thread
    constexpr int K  = FIELD * FK;

    unsigned long long acc[NP][4];
    #pragma unroll
    for (int p = 0; p < NP; p++)
        #pragma unroll
        for (int q = 0; q < 4; q++) acc[p][q] = 0ull;

    const int l0 = tr * TL;            // contiguous TL l's per thread
    const int d0 = tc * 4;             // 4 contiguous d's per thread

    for (int k0 = 0; k0 < K; k0 += KT) {
        const int kcnt = min(KT, K - k0);

        __syncthreads();   // previous tile fully consumed

        // ---- stage W tile: contiguous kcnt*L floats, float4 copy ----
        {
            const float4* src = (const float4*)(Wg + (size_t)k0 * L);
            float4*       dst = (float4*)Ws;
            const int n4 = (kcnt * L) >> 2;
            for (int t = tid; t < n4; t += NTHR) dst[t] = src[t];
        }
        // ---- build B tile: Bs[kk][d] = x0[i,d]*hprev[j,d], k=(i*FK+j) ----
        for (int t = tid; t < kcnt * DIM; t += NTHR) {
            const int kk = t >> 6;
            const int d  = t & 63;
            const int gk = k0 + kk;
            const int i  = gk / FK;       // FK is compile-time -> mul/shift
            const int j  = gk - i * FK;
            Bs[t] = x0s[i * DIM + d] * hprev[j * DIM + d];
        }
        __syncthreads();

        // ---- register-blocked FMA over this k-tile ----
        #pragma unroll 4
        for (int kk = 0; kk < kcnt; kk++) {
            const float4 bf = *(const float4*)(Bs + kk * DIM + d0);
            unsigned long long bv[4];
            bv[0] = dup2(bf.x); bv[1] = dup2(bf.y);
            bv[2] = dup2(bf.z); bv[3] = dup2(bf.w);
            const float* wro = Ws + kk * L + l0;
            #pragma unroll
            for (int p = 0; p < NP; p++) {
                const unsigned long long wv =
                    *(const unsigned long long*)(wro + p * 2);
                #pragma unroll
                for (int q = 0; q < 4; q++) fma2(acc[p][q], wv, bv[q]);
            }
        }
    }

    __syncthreads();   // done reading hprev before (possible) overlap
    // ---- epilogue: add bias, store to hout (layout [l][d]) ----
    #pragma unroll
    for (int p = 0; p < NP; p++) {
        const int la = l0 + 2 * p;
        const float ba = bias[la];
        const float bb = bias[la + 1];
        #pragma unroll
        for (int q = 0; q < 4; q++) {
            const float2 v = unpack2(acc[p][q]);
            hout[la * DIM + d0 + q]       = v.x + ba;
            hout[(la + 1) * DIM + d0 + q] = v.y + bb;
        }
    }
}

__global__ void __launch_bounds__(NTHR, 1) cin_kernel(
    const void* __restrict__ feat_ids_raw,
    const float* __restrict__ emb,
    const float* __restrict__ W0, const float* __restrict__ b0,
    const float* __restrict__ W1, const float* __restrict__ b1,
    const float* __restrict__ W2, const float* __restrict__ b2,
    float* __restrict__ out)
{
    extern __shared__ float sm[];
    float* x0s = sm + OFF_X0;
    float* h0  = sm + OFF_H0;
    float* h1  = sm + OFF_H1;
    float* h2  = sm + OFF_H2;
    float* Ws  = sm + OFF_WS;
    float* Bs  = sm + OFF_BS;

    __shared__ long long sids[FIELD];
    __shared__ int is64flag;

    const int b   = blockIdx.x;
    const int tid = threadIdx.x;

    // Detect id element width (int64 vs int32): int64 ids < 13105 => every
    // high 32-bit word is zero; int32 ids make those words random nonzero.
    if (tid == 0) {
        const unsigned int* w = (const unsigned int*)feat_ids_raw;
        int f = 1;
        #pragma unroll
        for (int t = 0; t < 32; t++)
            if (w[2 * t + 1] != 0u) { f = 0; break; }
        is64flag = f;
    }
    __syncthreads();

    if (tid < FIELD) {
        long long id;
        if (is64flag)
            id = ((const long long*)feat_ids_raw)[(size_t)b * FIELD + tid];
        else
            id = ((const int*)feat_ids_raw)[(size_t)b * FIELD + tid];
        sids[tid] = id;
    }
    __syncthreads();

    // Gather x0 = emb[feat_ids[b]]  -> SMEM [39][64]
    for (int t = tid; t < FIELD * DIM; t += NTHR) {
        const int r = t >> 6;
        const int d = t & 63;
        x0s[t] = emb[(size_t)sids[r] * DIM + d];
    }
    __syncthreads();

    cin_layer<L0, FIELD>(W0, b0, x0s, x0s, h0, Ws, Bs);
    __syncthreads();
    cin_layer<L1, L0>(W1, b1, x0s, h0, h1, Ws, Bs);
    __syncthreads();
    cin_layer<L2, L1>(W2, b2, x0s, h1, h2, Ws, Bs);
    __syncthreads();

    // Final reduce over embedding dim, write [b, 448]
    float* outb = out + (size_t)b * LTOT;
    for (int l = tid; l < LTOT; l += NTHR) {
        const float* src = (l < L0) ? (h0 + l * DIM)
                         : (l < L0 + L1) ? (h1 + (l - L0) * DIM)
                         : (h2 + (l - L0 - L1) * DIM);
        float s = 0.f;
        #pragma unroll 8
        for (int d = 0; d < DIM; d++) s += src[d];
        outb[l] = s;
    }
}

extern "C" void kernel_launch(void* const* d_in, const int* in_sizes, int n_in,
                              void* d_out, int out_size) {
    const void*  feat = d_in[0];
    const float* emb  = (const float*)d_in[1];
    const float* W0   = (const float*)d_in[2];
    const float* b0   = (const float*)d_in[3];
    const float* W1   = (const float*)d_in[4];
    const float* b1   = (const float*)d_in[5];
    const float* W2   = (const float*)d_in[6];
    const float* b2   = (const float*)d_in[7];
    float* out = (float*)d_out;

    cudaFuncSetAttribute(cin_kernel,
                         cudaFuncAttributeMaxDynamicSharedMemorySize,
                         SMEM_BYTES);
    cin_kernel<<<BATCH, NTHR, SMEM_BYTES>>>(feat, emb, W0, b0, W1, b1,
                                            W2, b2, out);
}

// round 2
// speedup vs baseline: 1.0938x; 1.0938x over previous
#include <cuda_runtime.h>
#include <cstdint>

// CIN (xDeepFM) fused kernel: one CTA per batch row, 512 threads.
// x0 gather -> 3 CIN layers as SMEM-resident GEMMs with on-the-fly
// outer-product B generation, software-pipelined tile staging.

#define BATCH 2048
#define FIELD 39
#define DIM   64
#define KT    32          // k-tile
#define NTHR  512

#define L0 256
#define L1 128
#define L2 64
#define LTOT (L0 + L1 + L2)   // 448

#define WSTRIDE (KT * L0)     // 8192 floats per W buffer
#define BSTRIDE (KT * DIM)    // 2048 floats per B buffer

// ---- packed f32x2 helpers (Blackwell) ----
__device__ __forceinline__ unsigned long long dup2(float v) {
    unsigned long long r;
    asm("mov.b64 %0, {%1, %1};" : "=l"(r) : "f"(v));
    return r;
}
__device__ __forceinline__ void fma2(unsigned long long& d,
                                     unsigned long long a,
                                     unsigned long long b) {
    asm("fma.rn.f32x2 %0, %1, %2, %3;" : "=l"(d) : "l"(a), "l"(b), "l"(d));
}
__device__ __forceinline__ float2 unpack2(unsigned long long v) {
    float2 f;
    asm("mov.b64 {%0, %1}, %2;" : "=f"(f.x), "=f"(f.y) : "l"(v));
    return f;
}

// SMEM layout (floats)
#define OFF_X0 0
#define OFF_H0 (OFF_X0 + FIELD * DIM)          // 2496
#define OFF_H1 (OFF_H0 + L0 * DIM)             // +16384
#define OFF_H2 (OFF_H1 + L1 * DIM)             // +8192
#define OFF_WS (OFF_H2 + L2 * DIM)             // +4096
#define OFF_BS (OFF_WS + 2 * WSTRIDE)          // +16384
#define SMEM_FLOATS (OFF_BS + 2 * BSTRIDE)     // +4096
#define SMEM_BYTES (SMEM_FLOATS * 4)           // 206,592 B

// One CIN layer: C[L,64] = W^T[L,K] * P[K,64], P[(i,j),d]=x0[i,d]*hprev[j,d]
// W row-major [K, L]. Software-pipelined: next W tile is LDG'd into regs
// before computing the current tile; STS + B-build happen after compute.
template<int L, int FK>
__device__ __forceinline__ void cin_layer(
    const float* __restrict__ Wg, const float* __restrict__ bias,
    const float* __restrict__ x0s, const float* __restrict__ hprev,
    float* __restrict__ hout, float* __restrict__ Ws, float* __restrict__ Bs)
{
    const int tid = threadIdx.x;
    const int tr  = tid >> 4;          // 0..31 -> l-group
    const int tc  = tid & 15;          // 0..15 -> d-group
    constexpr int TL = L / 32;         // l's per thread (8/4/2)
    constexpr int NP = TL / 2;         // packed l-pairs (4/2/1)
    constexpr int K  = FIELD * FK;
    constexpr int T  = (K + KT - 1) / KT;
    constexpr int NW4 = (KT * L) / (4 * NTHR);  // float4 per thread per full tile (4/2/1)

    unsigned long long acc[NP][4];
    #pragma unroll
    for (int p = 0; p < NP; p++)
        #pragma unroll
        for (int q = 0; q < 4; q++) acc[p][q] = 0ull;

    const int l0 = tr * TL;
    const int d0 = tc * 4;

    float4 wreg[NW4];

    // ---- prologue: stage tile 0 ----
    {
        const int n4 = min(KT, K) * L / 4;
        const float4* src = (const float4*)Wg;
        #pragma unroll
        for (int u = 0; u < NW4; u++) {
            const int idx = tid + u * NTHR;
            if (idx < n4) { wreg[u] = src[idx]; ((float4*)Ws)[idx] = wreg[u]; }
        }
        const int n = min(KT, K) * DIM;
        for (int e = tid; e < n; e += NTHR) {
            const int kk = e >> 6, d = e & 63;
            const int i = kk / FK, j = kk - i * FK;
            Bs[e] = x0s[i * DIM + d] * hprev[j * DIM + d];
        }
    }
    __syncthreads();

    for (int t = 0; t < T; t++) {
        const int cur = t & 1;
        const int nxt = cur ^ 1;
        const int kcnt = min(KT, K - t * KT);
        const bool more = (t + 1 < T);
        const int nk0 = (t + 1) * KT;
        const int nn4 = more ? (min(KT, K - nk0) * L / 4) : 0;

        // issue next tile's W LDGs early (latency hides behind compute)
        if (more) {
            const float4* src = (const float4*)(Wg + (size_t)nk0 * L);
            #pragma unroll
            for (int u = 0; u < NW4; u++) {
                const int idx = tid + u * NTHR;
                if (idx < nn4) wreg[u] = src[idx];
            }
        }

        // ---- compute current tile ----
        {
            const float* Wsb = Ws + cur * WSTRIDE;
            const float* Bsb = Bs + cur * BSTRIDE;
            #pragma unroll 4
            for (int kk = 0; kk < kcnt; kk++) {
                const float4 bf = *(const float4*)(Bsb + kk * DIM + d0);
                unsigned long long bv[4];
                bv[0] = dup2(bf.x); bv[1] = dup2(bf.y);
                bv[2] = dup2(bf.z); bv[3] = dup2(bf.w);
                const float* wro = Wsb + kk * L + l0;
                #pragma unroll
                for (int p = 0; p < NP; p++) {
                    const unsigned long long wv =
                        *(const unsigned long long*)(wro + p * 2);
                    #pragma unroll
                    for (int q = 0; q < 4; q++) fma2(acc[p][q], wv, bv[q]);
                }
            }
        }

        // ---- commit next tile to SMEM ----
        if (more) {
            float4* dst = (float4*)(Ws + nxt * WSTRIDE);
            #pragma unroll
            for (int u = 0; u < NW4; u++) {
                const int idx = tid + u * NTHR;
                if (idx < nn4) dst[idx] = wreg[u];
            }
            float* Bsb = Bs + nxt * BSTRIDE;
            const int n = min(KT, K - nk0) * DIM;
            for (int e = tid; e < n; e += NTHR) {
                const int kk = e >> 6, d = e & 63;
                const int gk = nk0 + kk;
                const int i = gk / FK, j = gk - i * FK;
                Bsb[e] = x0s[i * DIM + d] * hprev[j * DIM + d];
            }
        }
        __syncthreads();
    }

    // ---- epilogue: add bias, store to hout [l][d] ----
    #pragma unroll
    for (int p = 0; p < NP; p++) {
        const int la = l0 + 2 * p;
        const float ba = bias[la];
        const float bb = bias[la + 1];
        #pragma unroll
        for (int q = 0; q < 4; q++) {
            const float2 v = unpack2(acc[p][q]);
            hout[la * DIM + d0 + q]       = v.x + ba;
            hout[(la + 1) * DIM + d0 + q] = v.y + bb;
        }
    }
}

__global__ void __launch_bounds__(NTHR, 1) cin_kernel(
    const void* __restrict__ feat_ids_raw,
    const float* __restrict__ emb,
    const float* __restrict__ W0, const float* __restrict__ b0,
    const float* __restrict__ W1, const float* __restrict__ b1,
    const float* __restrict__ W2, const float* __restrict__ b2,
    float* __restrict__ out)
{
    extern __shared__ float sm[];
    float* x0s = sm + OFF_X0;
    float* h0  = sm + OFF_H0;
    float* h1  = sm + OFF_H1;
    float* h2  = sm + OFF_H2;
    float* Ws  = sm + OFF_WS;
    float* Bs  = sm + OFF_BS;

    __shared__ long long sids[FIELD];
    __shared__ int is64flag;

    const int b   = blockIdx.x;
    const int tid = threadIdx.x;

    // Detect id element width (int64 vs int32): int64 ids < 13105 => every
    // high 32-bit word is zero.
    if (tid == 0) {
        const unsigned int* w = (const unsigned int*)feat_ids_raw;
        int f = 1;
        #pragma unroll
        for (int t = 0; t < 32; t++)
            if (w[2 * t + 1] != 0u) { f = 0; break; }
        is64flag = f;
    }
    __syncthreads();

    if (tid < FIELD) {
        long long id;
        if (is64flag)
            id = ((const long long*)feat_ids_raw)[(size_t)b * FIELD + tid];
        else
            id = ((const int*)feat_ids_raw)[(size_t)b * FIELD + tid];
        sids[tid] = id;
    }
    __syncthreads();

    // Gather x0 = emb[feat_ids[b]]  -> SMEM [39][64]
    for (int t = tid; t < FIELD * DIM; t += NTHR) {
        const int r = t >> 6;
        const int d = t & 63;
        x0s[t] = emb[(size_t)sids[r] * DIM + d];
    }
    __syncthreads();

    cin_layer<L0, FIELD>(W0, b0, x0s, x0s, h0, Ws, Bs);
    __syncthreads();
    cin_layer<L1, L0>(W1, b1, x0s, h0, h1, Ws, Bs);
    __syncthreads();
    cin_layer<L2, L1>(W2, b2, x0s, h1, h2, Ws, Bs);
    __syncthreads();

    // Final reduce over embedding dim, write [b, 448]
    float* outb = out + (size_t)b * LTOT;
    for (int l = tid; l < LTOT; l += NTHR) {
        const float* src = (l < L0) ? (h0 + l * DIM)
                         : (l < L0 + L1) ? (h1 + (l - L0) * DIM)
                         : (h2 + (l - L0 - L1) * DIM);
        float s = 0.f;
        #pragma unroll 8
        for (int d = 0; d < DIM; d++) s += src[d];
        outb[l] = s;
    }
}

extern "C" void kernel_launch(void* const* d_in, const int* in_sizes, int n_in,
                              void* d_out, int out_size) {
    const void*  feat = d_in[0];
    const float* emb  = (const float*)d_in[1];
    const float* W0   = (const float*)d_in[2];
    const float* b0   = (const float*)d_in[3];
    const float* W1   = (const float*)d_in[4];
    const float* b1   = (const float*)d_in[5];
    const float* W2   = (const float*)d_in[6];
    const float* b2   = (const float*)d_in[7];
    float* out = (float*)d_out;

    cudaFuncSetAttribute(cin_kernel,
                         cudaFuncAttributeMaxDynamicSharedMemorySize,
                         SMEM_BYTES);
    cin_kernel<<<BATCH, NTHR, SMEM_BYTES>>>(feat, emb, W0, b0, W1, b1,
                                            W2, b2, out);
}